// round 3
// baseline (speedup 1.0000x reference)
#include <cuda_runtime.h>

#define NN 50000
#define NE 800000
#define NF 256
#define NCLS 47

// ---------------- scratch (device globals; no allocation allowed) ----------
__device__ __align__(16) float g_h1[NN * NF];   // layer outputs / logits reuse
__device__ __align__(16) float g_h2[NN * NF];
__device__ __align__(16) float g_hm[NN * NF];   // hmean buffer
__device__ float g_rdeg[NN];
__device__ int   g_rowstart[NN + 1];
__device__ int   g_cursor[NN];
__device__ int   g_adj[NE];
__device__ int   g_cnt[NN];

// select a scratch/input matrix in device code (no host symbol lookups)
__device__ __forceinline__ const float* sel_src(int sel, const float* x) {
    if (sel == 0) return x;
    if (sel == 1) return g_h1;
    return g_h2;
}
__device__ __forceinline__ float* sel_dst(int sel) {
    return (sel == 1) ? g_h1 : g_h2;
}

// ---------------- CSR build ----------------
__global__ void k_zero_cnt() {
    int i = blockIdx.x * blockDim.x + threadIdx.x;
    if (i < NN) g_cnt[i] = 0;
}

__global__ void k_count(const int* __restrict__ dst) {
    int e = blockIdx.x * blockDim.x + threadIdx.x;
    if (e < NE) {
        int d = dst[e];
        if (d >= 0 && d < NN) atomicAdd(&g_cnt[d], 1);
    }
}

// single-block exclusive scan over g_cnt -> g_rowstart, also rdeg + cursor init
__global__ void k_scan() {
    __shared__ int sbuf[1024];
    __shared__ int s_total;
    int tid = threadIdx.x;
    if (tid == 0) s_total = 0;
    __syncthreads();
    for (int base = 0; base < NN; base += 1024) {
        int i = base + tid;
        int v = (i < NN) ? g_cnt[i] : 0;
        sbuf[tid] = v;
        __syncthreads();
        for (int off = 1; off < 1024; off <<= 1) {
            int tval = (tid >= off) ? sbuf[tid - off] : 0;
            __syncthreads();
            sbuf[tid] += tval;
            __syncthreads();
        }
        int incl = sbuf[tid];
        int excl = incl - v;
        if (i < NN) {
            int rs = s_total + excl;
            g_rowstart[i] = rs;
            g_cursor[i]   = rs;
            g_rdeg[i]     = 1.0f / fmaxf((float)v, 1.0f);
        }
        __syncthreads();
        if (tid == 1023) s_total += incl;
        __syncthreads();
    }
    if (tid == 0) g_rowstart[NN] = s_total;
}

__global__ void k_fill(const int* __restrict__ src,
                       const int* __restrict__ dst) {
    int e = blockIdx.x * blockDim.x + threadIdx.x;
    if (e < NE) {
        int d = dst[e];
        int s = src[e];
        if (d >= 0 && d < NN && s >= 0 && s < NN) {
            int pos = atomicAdd(&g_cursor[d], 1);
            if (pos >= 0 && pos < NE) g_adj[pos] = s;
        }
    }
}

// ---------------- mean aggregation: one warp per node --------------------
// src_sel: 0 -> x (param), 1 -> g_h1, 2 -> g_h2. Output: g_hm.
__global__ void k_aggregate(int src_sel, const float* __restrict__ x) {
    const float* h = sel_src(src_sel, x);
    int w = (blockIdx.x * blockDim.x + threadIdx.x) >> 5;
    int lane = threadIdx.x & 31;
    if (w >= NN) return;
    int s0 = g_rowstart[w];
    int s1 = g_rowstart[w + 1];
    float4 a0 = make_float4(0.f, 0.f, 0.f, 0.f);
    float4 a1 = make_float4(0.f, 0.f, 0.f, 0.f);
    for (int j = s0; j < s1; j++) {
        int s = g_adj[j];
        const float4* row = (const float4*)(h + (size_t)s * NF);
        float4 v0 = row[lane];
        float4 v1 = row[lane + 32];
        a0.x += v0.x; a0.y += v0.y; a0.z += v0.z; a0.w += v0.w;
        a1.x += v1.x; a1.y += v1.y; a1.z += v1.z; a1.w += v1.w;
    }
    float r = g_rdeg[w];
    a0.x *= r; a0.y *= r; a0.z *= r; a0.w *= r;
    a1.x *= r; a1.y *= r; a1.z *= r; a1.w *= r;
    float4* o = (float4*)(g_hm + (size_t)w * NF);
    o[lane] = a0;
    o[lane + 32] = a1;
}

// ---------------- fused GEMM: C = [A | hmean] @ [Bw ; Bn] + bias (+SELU) ---
// A: [M, 256] row-major (sel). Bw, Bn: [256, Nc] row-major. C: [M, Nc] (sel).
// BM=128, BN=64, BK=16, 256 threads, 8x4 per-thread micro-tile.
__global__ void __launch_bounds__(256)
k_gemm(int a_sel, const float* __restrict__ x,
       const float* __restrict__ Bw, const float* __restrict__ Bn,
       const float* __restrict__ bias, int c_sel,
       int M, int Nc, int act) {
    const float* A  = sel_src(a_sel, x);
    const float* Am = g_hm;
    float* Cout = sel_dst(c_sel);

    __shared__ float As[16][128];
    __shared__ float Bs[16][64];

    int t  = threadIdx.x;
    int tm = t >> 4;        // 0..15
    int tn = t & 15;        // 0..15
    int bm = blockIdx.x * 128;
    int bn = blockIdx.y * 64;

    float acc[8][4];
#pragma unroll
    for (int i = 0; i < 8; i++)
#pragma unroll
        for (int j = 0; j < 4; j++) acc[i][j] = 0.f;

    int arow = t >> 1;            // 0..127
    int kofs = (t & 1) * 8;       // 0 or 8
    int bk   = t >> 4;            // 0..15
    int bnl  = (t & 15) * 4;      // 0..60

    for (int kt = 0; kt < 32; kt++) {
        const float* Ap = (kt < 16) ? A : Am;
        const float* Bp = (kt < 16) ? Bw : Bn;
        int kb = (kt & 15) * 16;

        // A tile load (global -> regs)
        float4 va0 = make_float4(0.f, 0.f, 0.f, 0.f);
        float4 va1 = make_float4(0.f, 0.f, 0.f, 0.f);
        int m = bm + arow;
        if (m < M) {
            const float* p = Ap + (size_t)m * NF + kb + kofs;
            va0 = *(const float4*)p;
            va1 = *(const float4*)(p + 4);
        }
        // B tile load (global -> regs), scalar with column guard
        float vb[4];
        {
            int krow = kb + bk;
            const float* p = Bp + (size_t)krow * Nc;
#pragma unroll
            for (int j = 0; j < 4; j++) {
                int c = bn + bnl + j;
                vb[j] = (c < Nc) ? p[c] : 0.f;
            }
        }

        __syncthreads();
        As[kofs + 0][arow] = va0.x;
        As[kofs + 1][arow] = va0.y;
        As[kofs + 2][arow] = va0.z;
        As[kofs + 3][arow] = va0.w;
        As[kofs + 4][arow] = va1.x;
        As[kofs + 5][arow] = va1.y;
        As[kofs + 6][arow] = va1.z;
        As[kofs + 7][arow] = va1.w;
#pragma unroll
        for (int j = 0; j < 4; j++) Bs[bk][bnl + j] = vb[j];
        __syncthreads();

#pragma unroll
        for (int kk = 0; kk < 16; kk++) {
            float4 a0 = *(const float4*)&As[kk][tm * 8];
            float4 a1 = *(const float4*)&As[kk][tm * 8 + 4];
            float4 b0 = *(const float4*)&Bs[kk][tn * 4];
            float av[8] = {a0.x, a0.y, a0.z, a0.w, a1.x, a1.y, a1.z, a1.w};
            float bv[4] = {b0.x, b0.y, b0.z, b0.w};
#pragma unroll
            for (int i = 0; i < 8; i++)
#pragma unroll
                for (int j = 0; j < 4; j++)
                    acc[i][j] = fmaf(av[i], bv[j], acc[i][j]);
        }
    }

    const float kAlpha  = 1.6732632423543772f;
    const float kLambda = 1.0507009873554805f;
#pragma unroll
    for (int i = 0; i < 8; i++) {
        int m = bm + tm * 8 + i;
        if (m >= M) continue;
#pragma unroll
        for (int j = 0; j < 4; j++) {
            int c = bn + tn * 4 + j;
            if (c >= Nc) continue;
            float v = acc[i][j] + bias[c];
            if (act == 1) {
                v = (v > 0.f) ? kLambda * v
                              : kLambda * kAlpha * (expf(v) - 1.f);
            }
            Cout[(size_t)m * Nc + c] = v;
        }
    }
}

// ---------------- softmax over 47 classes (logits in g_h1) -----------------
__global__ void k_softmax(float* __restrict__ out) {
    int w = (blockIdx.x * blockDim.x + threadIdx.x) >> 5;
    int lane = threadIdx.x & 31;
    if (w >= NN) return;
    const float* z = g_h1 + (size_t)w * NCLS;
    float v0 = (lane < NCLS) ? z[lane] : -1e30f;
    float v1 = (lane + 32 < NCLS) ? z[lane + 32] : -1e30f;
    float m = fmaxf(v0, v1);
#pragma unroll
    for (int o = 16; o; o >>= 1) m = fmaxf(m, __shfl_xor_sync(0xffffffffu, m, o));
    float e0 = (lane < NCLS) ? expf(v0 - m) : 0.f;
    float e1 = (lane + 32 < NCLS) ? expf(v1 - m) : 0.f;
    float s = e0 + e1;
#pragma unroll
    for (int o = 16; o; o >>= 1) s += __shfl_xor_sync(0xffffffffu, s, o);
    float inv = 1.f / s;
    if (lane < NCLS)       out[(size_t)w * NCLS + lane]      = e0 * inv;
    if (lane + 32 < NCLS)  out[(size_t)w * NCLS + lane + 32] = e1 * inv;
}

// ---------------- launch ---------------------------------------------------
extern "C" void kernel_launch(void* const* d_in, const int* in_sizes, int n_in,
                              void* d_out, int out_size) {
    const float* x   = (const float*)d_in[0];
    const int*   src = (const int*)d_in[1];    // JAX default x64-disabled: int32
    const int*   dst = (const int*)d_in[2];
    const float* Ws0 = (const float*)d_in[3];
    const float* Wn0 = (const float*)d_in[4];
    const float* b0  = (const float*)d_in[5];
    const float* Ws1 = (const float*)d_in[6];
    const float* Wn1 = (const float*)d_in[7];
    const float* b1  = (const float*)d_in[8];
    const float* Ws2 = (const float*)d_in[9];
    const float* Wn2 = (const float*)d_in[10];
    const float* b2  = (const float*)d_in[11];
    float* out = (float*)d_out;

    // CSR build (per call)
    k_zero_cnt<<<(NN + 255) / 256, 256>>>();
    k_count<<<(NE + 255) / 256, 256>>>(dst);
    k_scan<<<1, 1024>>>();
    k_fill<<<(NE + 255) / 256, 256>>>(src, dst);

    dim3 gemm_grid_full((NN + 127) / 128, NF / 64);
    dim3 gemm_grid_last((NN + 127) / 128, 1);
    int agg_blocks = (NN + 7) / 8;   // 8 warps per 256-thread block

    // layer 0: x -> g_h1
    k_aggregate<<<agg_blocks, 256>>>(0, x);
    k_gemm<<<gemm_grid_full, 256>>>(0, x, Ws0, Wn0, b0, 1, NN, NF, 1);

    // layer 1: g_h1 -> g_h2
    k_aggregate<<<agg_blocks, 256>>>(1, x);
    k_gemm<<<gemm_grid_full, 256>>>(1, x, Ws1, Wn1, b1, 2, NN, NF, 1);

    // layer 2: g_h2 -> logits in g_h1 (reused as [NN, 47])
    k_aggregate<<<agg_blocks, 256>>>(2, x);
    k_gemm<<<gemm_grid_last, 256>>>(2, x, Ws2, Wn2, b2, 1, NN, NCLS, 0);

    // softmax -> d_out
    k_softmax<<<agg_blocks, 256>>>(out);
}